// round 5
// baseline (speedup 1.0000x reference)
#include <cuda_runtime.h>
#include <cuda_bf16.h>
#include <math_constants.h>

static constexpr int BB = 4;
static constexpr int SS = 2048;
static constexpr int DD = 1024;

// Scratch: __device__ globals (allocation inside kernel_launch is forbidden).
__device__ float g_q[(size_t)BB * SS * DD];    // 32 MB
__device__ float g_k[(size_t)BB * SS * DD];    // 32 MB
__device__ float g_v[(size_t)BB * SS * DD];    // 32 MB
__device__ float g_sc[(size_t)BB * SS * SS];   // 64 MB
__device__ int   g_mask_mode;                  // 0=u8, 1=i32, 2=f32, 3=bf16

// ---------------------------------------------------------------------------
// Mask dtype detection. The harness widens jnp.bool_ to an unknown dtype.
// Scan only the first BB*SS bytes (valid under every candidate layout) and
// use the byte signature of the value 1 in each encoding:
//   u8   : value bytes 0/1 at every index        -> nonzero at i%4!=0, no 0x3F
//   i32  : 1 = [01 00 00 00]                     -> all i%4!=0 bytes are 0
//   f32  : 1.0f = [00 00 80 3F]                  -> 0x3F at i%4==3 (not i%4==1)
//   bf16 : 1.0  = [80 3F] per element            -> 0x3F at i%4==1
// ---------------------------------------------------------------------------
__global__ void detect_mask_kernel(const unsigned char* __restrict__ m)
{
    __shared__ int fA, f3, f1;
    if (threadIdx.x == 0) { fA = 0; f3 = 0; f1 = 0; }
    __syncthreads();
    for (int i = threadIdx.x; i < BB * SS; i += 256) {
        unsigned char b = m[i];
        int r = i & 3;
        if (r != 0 && b != 0) fA = 1;
        if (r == 3 && b == 0x3F) f3 = 1;
        if (r == 1 && b == 0x3F) f1 = 1;
    }
    __syncthreads();
    if (threadIdx.x == 0) {
        int mode;
        if (f1)      mode = 3;   // bf16
        else if (f3) mode = 2;   // f32
        else if (fA) mode = 0;   // u8
        else         mode = 1;   // i32 (also covers the all-false degenerate case)
        g_mask_mode = mode;
    }
}

__device__ __forceinline__ int mask_value(const void* m, long row)
{
    switch (g_mask_mode) {
        case 1:  return ((const int*)m)[row] != 0;
        case 2:  return ((const float*)m)[row] != 0.0f;
        case 3:  return ((const unsigned short*)m)[row] != 0;
        default: return ((const unsigned char*)m)[row] != 0;
    }
}

// ---------------------------------------------------------------------------
// Tiled SGEMM: C = alpha * A @ B(T)
//   BM=BN=128, BK=8, 256 threads, 8x8 micro-tile per thread.
//   TRANS_B=false: B is [K,N] row-major. TRANS_B=true: B is [N,K] row-major.
//   blockIdx.z batches via strides sA/sB/sC.
// ---------------------------------------------------------------------------
template <bool TRANS_B>
__global__ __launch_bounds__(256, 2)
void sgemm_kernel(const float* __restrict__ Ag, const float* __restrict__ Bg,
                  float* __restrict__ Cg, int M, int N, int K,
                  long sA, long sB, long sC, float alpha)
{
    constexpr int BM = 128, BN = 128, BK = 8;

    const float* A = Ag + (long)blockIdx.z * sA;
    const float* B = Bg + (long)blockIdx.z * sB;
    float*       C = Cg + (long)blockIdx.z * sC;

    __shared__ float As[BK][BM];
    __shared__ float Bs[BK][BN];

    const int tid = threadIdx.x;
    const int tx = tid & 15;        // 0..15  -> 8 cols each
    const int ty = tid >> 4;        // 0..15  -> 8 rows each
    const int rowBase = blockIdx.y * BM;
    const int colBase = blockIdx.x * BN;

    float acc[8][8];
#pragma unroll
    for (int i = 0; i < 8; i++)
#pragma unroll
        for (int j = 0; j < 8; j++) acc[i][j] = 0.0f;

    // A-tile load mapping: 128 rows x 8 k, one float4 per thread
    const int aRow = tid >> 1;          // 0..127
    const int aCol = (tid & 1) * 4;     // 0 or 4
    // B-tile load mapping (NN): 8 k-rows x 128 cols
    const int bRow = tid >> 5;          // 0..7
    const int bCol = (tid & 31) * 4;    // 0..124

    for (int k0 = 0; k0 < K; k0 += BK) {
        // --- load A tile (transposed into As[k][m]) ---
        float4 av = *(const float4*)&A[(long)(rowBase + aRow) * K + k0 + aCol];
        As[aCol + 0][aRow] = av.x;
        As[aCol + 1][aRow] = av.y;
        As[aCol + 2][aRow] = av.z;
        As[aCol + 3][aRow] = av.w;

        // --- load B tile ---
        if (TRANS_B) {
            // B is [N,K]: row (colBase+n) gives Bs[k][n]
            float4 bv = *(const float4*)&B[(long)(colBase + aRow) * K + k0 + aCol];
            Bs[aCol + 0][aRow] = bv.x;
            Bs[aCol + 1][aRow] = bv.y;
            Bs[aCol + 2][aRow] = bv.z;
            Bs[aCol + 3][aRow] = bv.w;
        } else {
            // B is [K,N]
            *(float4*)&Bs[bRow][bCol] =
                *(const float4*)&B[(long)(k0 + bRow) * N + colBase + bCol];
        }
        __syncthreads();

#pragma unroll
        for (int kk = 0; kk < BK; kk++) {
            float a[8], b[8];
#pragma unroll
            for (int i = 0; i < 8; i++) a[i] = As[kk][ty * 8 + i];
#pragma unroll
            for (int j = 0; j < 8; j++) b[j] = Bs[kk][tx * 8 + j];
#pragma unroll
            for (int i = 0; i < 8; i++)
#pragma unroll
                for (int j = 0; j < 8; j++) acc[i][j] = fmaf(a[i], b[j], acc[i][j]);
        }
        __syncthreads();
    }

    // --- write back (two float4 per row) ---
#pragma unroll
    for (int i = 0; i < 8; i++) {
        long cOff = (long)(rowBase + ty * 8 + i) * N + colBase + tx * 8;
        float4 v0 = make_float4(alpha * acc[i][0], alpha * acc[i][1],
                                alpha * acc[i][2], alpha * acc[i][3]);
        float4 v1 = make_float4(alpha * acc[i][4], alpha * acc[i][5],
                                alpha * acc[i][6], alpha * acc[i][7]);
        *(float4*)&C[cOff]     = v0;
        *(float4*)&C[cOff + 4] = v1;
    }
}

// ---------------------------------------------------------------------------
// Row softmax over the last axis (S=2048), in place. One block per row.
//
// Numerical subtlety: the reference adds -1e9 (fp32) to every score of a
// masked query row BEFORE softmax. At magnitude 1e9 the fp32 ulp is 64, and
// scores are ~N(0,1), so (score - 1e9) rounds to EXACTLY -1e9 for the whole
// row -> softmax becomes exactly uniform (1/S). We reproduce this by doing
// the identical fp32 add for masked rows.
// ---------------------------------------------------------------------------
__global__ __launch_bounds__(256)
void softmax_kernel(float* __restrict__ sc, const void* __restrict__ mask)
{
    const long row = (long)blockIdx.y * SS + blockIdx.x;
    float* p = sc + row * SS;
    const int tid = threadIdx.x;
    const int lane = tid & 31;
    const int warp = tid >> 5;
    __shared__ float red[8];

    // additive mask term, applied in fp32 exactly as the reference does
    const float madd = mask_value(mask, row) ? 0.0f : -1e9f;

    // --- pass 1: apply mask add (in place) + max ---
    float m = -CUDART_INF_F;
    for (int i = tid; i < SS; i += 256) {
        float s = p[i] + madd;   // fp32 rounding intentional (matches reference)
        p[i] = s;
        m = fmaxf(m, s);
    }
#pragma unroll
    for (int o = 16; o > 0; o >>= 1) m = fmaxf(m, __shfl_xor_sync(0xffffffffu, m, o));
    if (lane == 0) red[warp] = m;
    __syncthreads();
    m = red[lane & 7];
#pragma unroll
    for (int o = 4; o > 0; o >>= 1) m = fmaxf(m, __shfl_xor_sync(0xffffffffu, m, o));
    m = __shfl_sync(0xffffffffu, m, 0);

    // --- pass 2: exp + sum ---
    float sum = 0.0f;
    for (int i = tid; i < SS; i += 256) {
        float e = __expf(p[i] - m);
        p[i] = e;
        sum += e;
    }
#pragma unroll
    for (int o = 16; o > 0; o >>= 1) sum += __shfl_xor_sync(0xffffffffu, sum, o);
    __syncthreads();
    if (lane == 0) red[warp] = sum;
    __syncthreads();
    sum = red[lane & 7];
#pragma unroll
    for (int o = 4; o > 0; o >>= 1) sum += __shfl_xor_sync(0xffffffffu, sum, o);
    const float inv = 1.0f / __shfl_sync(0xffffffffu, sum, 0);

    for (int i = tid; i < SS; i += 256) p[i] *= inv;
}

// ---------------------------------------------------------------------------
// kernel_launch
// Inputs (metadata order): x [B,S,D] f32, mask [B,S] bool (dtype detected),
//                          q_w [D,D] f32, k_w [D,D] f32, v_w [D,D] f32
// Output: [B,S,D] f32
// ---------------------------------------------------------------------------
extern "C" void kernel_launch(void* const* d_in, const int* in_sizes, int n_in,
                              void* d_out, int out_size)
{
    (void)in_sizes; (void)n_in; (void)out_size;
    const float* x    = (const float*)d_in[0];
    const void*  mask = d_in[1];
    const float* qw   = (const float*)d_in[2];
    const float* kw   = (const float*)d_in[3];
    const float* vw   = (const float*)d_in[4];
    float* out = (float*)d_out;

    float *q, *k, *v, *sc;
    cudaGetSymbolAddress((void**)&q,  g_q);
    cudaGetSymbolAddress((void**)&k,  g_k);
    cudaGetSymbolAddress((void**)&v,  g_v);
    cudaGetSymbolAddress((void**)&sc, g_sc);

    const float scale = 0.03125f;  // 1/sqrt(1024)
    dim3 blk(256);

    // Detect mask storage dtype (writes g_mask_mode)
    detect_mask_kernel<<<1, 256>>>((const unsigned char*)mask);

    // QKV projections: [8192,1024] x [1024,1024]
    dim3 gProj(DD / 128, (BB * SS) / 128, 1);
    sgemm_kernel<false><<<gProj, blk>>>(x, qw, q, BB * SS, DD, DD, 0, 0, 0, 1.0f);
    sgemm_kernel<false><<<gProj, blk>>>(x, kw, k, BB * SS, DD, DD, 0, 0, 0, 1.0f);
    sgemm_kernel<false><<<gProj, blk>>>(x, vw, v, BB * SS, DD, DD, 0, 0, 0, 1.0f);

    // Scores: per-batch Q[2048,1024] x K^T -> [2048,2048], scaled
    dim3 gSc(SS / 128, SS / 128, BB);
    sgemm_kernel<true><<<gSc, blk>>>(q, k, sc, SS, SS, DD,
                                     (long)SS * DD, (long)SS * DD, (long)SS * SS,
                                     scale);

    // Softmax rows (with reference-exact fp32 mask add)
    softmax_kernel<<<dim3(SS, BB), blk>>>(sc, mask);

    // Out: per-batch P[2048,2048] x V[2048,1024]
    dim3 gPV(DD / 128, SS / 128, BB);
    sgemm_kernel<false><<<gPV, blk>>>(sc, v, out, SS, DD, SS,
                                      (long)SS * SS, (long)SS * DD, (long)SS * DD,
                                      1.0f);
}

// round 9
// speedup vs baseline: 2.4044x; 2.4044x over previous
#include <cuda_runtime.h>
#include <cuda_bf16.h>
#include <math_constants.h>
#include <cstdint>

static constexpr int BB = 4, SS = 2048, DD = 1024;

// ---------------- scratch (__device__ globals; no allocs allowed) ----------
__device__ __nv_bfloat16 g_xh[(size_t)BB*SS*DD], g_xl[(size_t)BB*SS*DD];
__device__ __nv_bfloat16 g_wqh[DD*DD], g_wql[DD*DD];
__device__ __nv_bfloat16 g_wkh[DD*DD], g_wkl[DD*DD];
__device__ __nv_bfloat16 g_wvh[DD*DD], g_wvl[DD*DD];
__device__ __nv_bfloat16 g_qh[(size_t)BB*SS*DD], g_ql[(size_t)BB*SS*DD];
__device__ __nv_bfloat16 g_kh[(size_t)BB*SS*DD], g_kl[(size_t)BB*SS*DD];
__device__ __nv_bfloat16 g_vth[(size_t)BB*DD*SS], g_vtl[(size_t)BB*DD*SS];   // V^T per batch
__device__ float         g_sc[(size_t)BB*SS*SS];
__device__ __nv_bfloat16 g_ph[(size_t)BB*SS*SS], g_pl[(size_t)BB*SS*SS];
__device__ int           g_mask_mode;

// ---------------- helpers ---------------------------------------------------
__device__ __forceinline__ uint32_t smem_u32(const void* p) {
    uint32_t a;
    asm("{ .reg .u64 t; cvta.to.shared.u64 t, %1; cvt.u32.u64 %0, t; }" : "=r"(a) : "l"(p));
    return a;
}
__device__ __forceinline__ void ldsm_x4(uint32_t* r, uint32_t addr) {
    asm volatile("ldmatrix.sync.aligned.m8n8.x4.shared.b16 {%0,%1,%2,%3}, [%4];"
                 : "=r"(r[0]), "=r"(r[1]), "=r"(r[2]), "=r"(r[3]) : "r"(addr));
}
__device__ __forceinline__ void mma16816(float* d, const uint32_t* a, const uint32_t* b) {
    asm volatile(
        "mma.sync.aligned.m16n8k16.row.col.f32.bf16.bf16.f32 "
        "{%0,%1,%2,%3}, {%4,%5,%6,%7}, {%8,%9}, {%0,%1,%2,%3};\n"
        : "+f"(d[0]), "+f"(d[1]), "+f"(d[2]), "+f"(d[3])
        : "r"(a[0]), "r"(a[1]), "r"(a[2]), "r"(a[3]), "r"(b[0]), "r"(b[1]));
}
__device__ __forceinline__ void split_bf16(float v, __nv_bfloat16& h, __nv_bfloat16& l) {
    h = __float2bfloat16(v);
    l = __float2bfloat16(v - __bfloat162float(h));
}

// ---------------- GEMM: C = alpha * (Ah+Al)[m,k] x (Bh+Bl)[n,k]^T ----------
// CTA 128x128, KC=32, 8 warps (warp tile 64x32), cp.async double buffer.
// Smem rows stride 80B (conflict-free ldmatrix). OUT: 0=f32*alpha, 1=bf16 hi/lo,
// 2=bf16 hi/lo transposed scatter (V^T).
static constexpr int KC = 32;
static constexpr int MAT_BYTES   = 128 * 80;          // 10240
static constexpr int STAGE_BYTES = 4 * MAT_BYTES;     // 40960
static constexpr int GEMM_SMEM   = 2 * STAGE_BYTES;   // 81920

template <int OUT>
__global__ __launch_bounds__(256, 1)
void gemm3_kernel(const __nv_bfloat16* __restrict__ Ah, const __nv_bfloat16* __restrict__ Al,
                  const __nv_bfloat16* __restrict__ Bh, const __nv_bfloat16* __restrict__ Bl,
                  float* __restrict__ Cf, __nv_bfloat16* __restrict__ Ch,
                  __nv_bfloat16* __restrict__ Cl,
                  int N, int K, long sA, long sB, long sC, float alpha)
{
    extern __shared__ char smem[];
    const uint32_t sb = smem_u32(smem);
    const int tid = threadIdx.x, lane = tid & 31, wid = tid >> 5;
    const int wm = wid & 1, wn = wid >> 1;             // warp tile: rows wm*64, cols wn*32
    const int z = blockIdx.z;
    const int tileM = blockIdx.y * 128, tileN = blockIdx.x * 128;

    const char* gA[2] = { (const char*)(Ah + (size_t)z*sA + (size_t)tileM*K),
                          (const char*)(Al + (size_t)z*sA + (size_t)tileM*K) };
    const char* gB[2] = { (const char*)(Bh + (size_t)z*sB + (size_t)tileN*K),
                          (const char*)(Bl + (size_t)z*sB + (size_t)tileN*K) };

    // per-thread copy coords: unit u = tid (+256); row=u>>2, seg=u&3 (16B each)
    const int crow = tid >> 2, cseg = tid & 3;
    const uint32_t d0 = (uint32_t)(crow * 80 + cseg * 16);
    const uint32_t d1 = d0 + 64 * 80;
    const size_t  s0 = ((size_t)crow * K + cseg * 8) * 2;   // bytes
    const size_t  s1 = s0 + (size_t)64 * K * 2;

    const int nch = K / KC;

#define CP16(dst, src) \
    asm volatile("cp.async.cg.shared.global [%0], [%1], 16;" :: "r"(dst), "l"(src) : "memory")

#define LOAD_CHUNK(c, stage) do {                                             \
    const uint32_t st_ = sb + (stage) * STAGE_BYTES;                          \
    const size_t ko_ = (size_t)(c) * KC * 2;                                  \
    CP16(st_ + 0*MAT_BYTES + d0, gA[0] + s0 + ko_);                           \
    CP16(st_ + 0*MAT_BYTES + d1, gA[0] + s1 + ko_);                           \
    CP16(st_ + 1*MAT_BYTES + d0, gA[1] + s0 + ko_);                           \
    CP16(st_ + 1*MAT_BYTES + d1, gA[1] + s1 + ko_);                           \
    CP16(st_ + 2*MAT_BYTES + d0, gB[0] + s0 + ko_);                           \
    CP16(st_ + 2*MAT_BYTES + d1, gB[0] + s1 + ko_);                           \
    CP16(st_ + 3*MAT_BYTES + d0, gB[1] + s0 + ko_);                           \
    CP16(st_ + 3*MAT_BYTES + d1, gB[1] + s1 + ko_);                           \
    asm volatile("cp.async.commit_group;" ::: "memory");                      \
} while (0)

    LOAD_CHUNK(0, 0);

    float acc[16][4];
#pragma unroll
    for (int i = 0; i < 16; ++i)
#pragma unroll
        for (int j = 0; j < 4; ++j) acc[i][j] = 0.0f;

    // ldmatrix per-lane address components (PTX fragment tables):
    // A x4: matrices (m0-7,k0-7),(m8-15,k0-7),(m0-7,k8-15),(m8-15,k8-15)
    const int arow = wm * 64 + (lane & 7) + ((lane >> 3) & 1) * 8;
    const int acol = ((lane >> 4) & 1) * 16;           // bytes (k+8 -> +16B)
    // B x4: matrices (n0-7,k0-7),(n0-7,k8-15),(n8-15,k0-7),(n8-15,k8-15)
    const int brow = wn * 32 + (lane & 7) + ((lane >> 4) & 1) * 8;
    const int bcol = ((lane >> 3) & 1) * 16;

#pragma unroll 1
    for (int c = 0; c < nch; ++c) {
        if (c + 1 < nch) {
            LOAD_CHUNK(c + 1, (c + 1) & 1);
            asm volatile("cp.async.wait_group 1;" ::: "memory");
        } else {
            asm volatile("cp.async.wait_group 0;" ::: "memory");
        }
        __syncthreads();

        const uint32_t st = sb + (c & 1) * STAGE_BYTES;
#pragma unroll
        for (int ks = 0; ks < 2; ++ks) {
            const int kb = ks * 32;                    // 16 bf16 = 32 B
            uint32_t ah[4][4], al[4][4], bh[2][4], bl[2][4];
#pragma unroll
            for (int mt = 0; mt < 4; ++mt) {
                const uint32_t ad = st + (uint32_t)((arow + mt * 16) * 80 + kb + acol);
                ldsm_x4(ah[mt], ad);
                ldsm_x4(al[mt], ad + MAT_BYTES);
            }
#pragma unroll
            for (int bt = 0; bt < 2; ++bt) {
                const uint32_t bd = st + 2 * MAT_BYTES +
                                    (uint32_t)((brow + bt * 16) * 80 + kb + bcol);
                ldsm_x4(bh[bt], bd);
                ldsm_x4(bl[bt], bd + MAT_BYTES);
            }
#pragma unroll
            for (int mt = 0; mt < 4; ++mt)
#pragma unroll
                for (int nt = 0; nt < 4; ++nt) {
                    float* d = acc[mt * 4 + nt];
                    const uint32_t* bhp = &bh[nt >> 1][(nt & 1) * 2];
                    const uint32_t* blp = &bl[nt >> 1][(nt & 1) * 2];
                    mma16816(d, ah[mt], bhp);
                    mma16816(d, ah[mt], blp);
                    mma16816(d, al[mt], bhp);
                }
        }
        __syncthreads();
    }
#undef LOAD_CHUNK
#undef CP16

    // ---------------- epilogue ----------------
    const int r0base = tileM + wm * 64, cbase = tileN + wn * 32;
#pragma unroll
    for (int mt = 0; mt < 4; ++mt)
#pragma unroll
        for (int nt = 0; nt < 4; ++nt) {
            const float* d = acc[mt * 4 + nt];
            const int row0 = r0base + mt * 16 + (lane >> 2);
            const int row1 = row0 + 8;
            const int col  = cbase + nt * 8 + (lane & 3) * 2;
            if (OUT == 0) {
                float* base = Cf + (size_t)z * sC;
                float2 v0 = make_float2(alpha * d[0], alpha * d[1]);
                float2 v1 = make_float2(alpha * d[2], alpha * d[3]);
                *reinterpret_cast<float2*>(base + (size_t)row0 * N + col) = v0;
                *reinterpret_cast<float2*>(base + (size_t)row1 * N + col) = v1;
            } else if (OUT == 1) {
                __nv_bfloat16 h0, l0, h1, l1, h2, l2, h3, l3;
                split_bf16(d[0], h0, l0); split_bf16(d[1], h1, l1);
                split_bf16(d[2], h2, l2); split_bf16(d[3], h3, l3);
                *reinterpret_cast<__nv_bfloat162*>(Ch + (size_t)row0 * N + col) =
                    __halves2bfloat162(h0, h1);
                *reinterpret_cast<__nv_bfloat162*>(Cl + (size_t)row0 * N + col) =
                    __halves2bfloat162(l0, l1);
                *reinterpret_cast<__nv_bfloat162*>(Ch + (size_t)row1 * N + col) =
                    __halves2bfloat162(h2, h3);
                *reinterpret_cast<__nv_bfloat162*>(Cl + (size_t)row1 * N + col) =
                    __halves2bfloat162(l2, l3);
            } else {   // OUT == 2: V^T — dst[(mb*DD + col)*SS + srow]
#pragma unroll
                for (int e = 0; e < 4; ++e) {
                    const int rr = (e < 2) ? row0 : row1;
                    const int cc = col + (e & 1);
                    const int mb = rr >> 11, srow = rr & (SS - 1);
                    __nv_bfloat16 h, l;
                    split_bf16(d[e], h, l);
                    const size_t o = ((size_t)mb * DD + cc) * SS + srow;
                    Ch[o] = h; Cl[o] = l;
                }
            }
        }
}

// ---------------- conversions ----------------------------------------------
__global__ void convert_split_kernel(const float* __restrict__ x,
                                     __nv_bfloat16* __restrict__ h,
                                     __nv_bfloat16* __restrict__ l, size_t n)
{
    size_t i = ((size_t)blockIdx.x * 256 + threadIdx.x) * 4;
    if (i >= n) return;
    float4 v = *reinterpret_cast<const float4*>(x + i);
    __nv_bfloat16 h0, l0, h1, l1, h2, l2, h3, l3;
    split_bf16(v.x, h0, l0); split_bf16(v.y, h1, l1);
    split_bf16(v.z, h2, l2); split_bf16(v.w, h3, l3);
    *reinterpret_cast<__nv_bfloat162*>(h + i)     = __halves2bfloat162(h0, h1);
    *reinterpret_cast<__nv_bfloat162*>(h + i + 2) = __halves2bfloat162(h2, h3);
    *reinterpret_cast<__nv_bfloat162*>(l + i)     = __halves2bfloat162(l0, l1);
    *reinterpret_cast<__nv_bfloat162*>(l + i + 2) = __halves2bfloat162(l2, l3);
}

// W [D,D] row-major -> W^T hi/lo bf16 (Th[n*D+k] = W[k][n])
__global__ void wtrans_split_kernel(const float* __restrict__ W,
                                    __nv_bfloat16* __restrict__ Th,
                                    __nv_bfloat16* __restrict__ Tl)
{
    __shared__ float t[32][33];
    const int bx = blockIdx.x * 32, by = blockIdx.y * 32;
    const int tx = threadIdx.x, ty = threadIdx.y;   // 32 x 8
#pragma unroll
    for (int i = 0; i < 32; i += 8)
        t[ty + i][tx] = W[(size_t)(by + ty + i) * DD + bx + tx];
    __syncthreads();
#pragma unroll
    for (int i = 0; i < 32; i += 8) {
        float v = t[tx][ty + i];                    // = W[by+tx][bx+ty+i]
        __nv_bfloat16 h, l;
        split_bf16(v, h, l);
        Th[(size_t)(bx + ty + i) * DD + by + tx] = h;
        Tl[(size_t)(bx + ty + i) * DD + by + tx] = l;
    }
}

// ---------------- mask dtype detection (validated in R5) -------------------
__global__ void detect_mask_kernel(const unsigned char* __restrict__ m)
{
    __shared__ int fA, f3, f1;
    if (threadIdx.x == 0) { fA = 0; f3 = 0; f1 = 0; }
    __syncthreads();
    for (int i = threadIdx.x; i < BB * SS; i += 256) {
        unsigned char b = m[i];
        int r = i & 3;
        if (r != 0 && b != 0) fA = 1;
        if (r == 3 && b == 0x3F) f3 = 1;
        if (r == 1 && b == 0x3F) f1 = 1;
    }
    __syncthreads();
    if (threadIdx.x == 0) {
        int mode;
        if (f1)      mode = 3;
        else if (f3) mode = 2;
        else if (fA) mode = 0;
        else         mode = 1;
        g_mask_mode = mode;
    }
}
__device__ __forceinline__ int mask_value(const void* m, long row)
{
    switch (g_mask_mode) {
        case 1:  return ((const int*)m)[row] != 0;
        case 2:  return ((const float*)m)[row] != 0.0f;
        case 3:  return ((const unsigned short*)m)[row] != 0;
        default: return ((const unsigned char*)m)[row] != 0;
    }
}

// ---------------- softmax (fp32 in, bf16 hi/lo out) -------------------------
// Masked rows: fp32 +(-1e9) collapses the row to exactly -1e9 (ulp=64) ->
// exactly uniform softmax, matching the reference bit-behavior.
__global__ __launch_bounds__(256)
void softmax_kernel(const float* __restrict__ sc, const void* __restrict__ mask,
                    __nv_bfloat16* __restrict__ ph, __nv_bfloat16* __restrict__ pl)
{
    const long row = (long)blockIdx.y * SS + blockIdx.x;
    const float* p = sc + (size_t)row * SS;
    const int tid = threadIdx.x, lane = tid & 31, warp = tid >> 5;
    __shared__ float red[8];

    const float madd = mask_value(mask, row) ? 0.0f : -1e9f;

    float r[8];
    float m = -CUDART_INF_F;
#pragma unroll
    for (int it = 0; it < 8; ++it) {
        float s = p[tid + it * 256] + madd;   // fp32 rounding intentional
        r[it] = s;
        m = fmaxf(m, s);
    }
#pragma unroll
    for (int o = 16; o > 0; o >>= 1) m = fmaxf(m, __shfl_xor_sync(0xffffffffu, m, o));
    if (lane == 0) red[warp] = m;
    __syncthreads();
    m = red[lane & 7];
#pragma unroll
    for (int o = 4; o > 0; o >>= 1) m = fmaxf(m, __shfl_xor_sync(0xffffffffu, m, o));
    m = __shfl_sync(0xffffffffu, m, 0);

    float sum = 0.0f;
#pragma unroll
    for (int it = 0; it < 8; ++it) {
        float e = __expf(r[it] - m);
        r[it] = e;
        sum += e;
    }
#pragma unroll
    for (int o = 16; o > 0; o >>= 1) sum += __shfl_xor_sync(0xffffffffu, sum, o);
    __syncthreads();
    if (lane == 0) red[warp] = sum;
    __syncthreads();
    sum = red[lane & 7];
#pragma unroll
    for (int o = 4; o > 0; o >>= 1) sum += __shfl_xor_sync(0xffffffffu, sum, o);
    const float inv = 1.0f / __shfl_sync(0xffffffffu, sum, 0);

    const size_t ro = (size_t)row * SS;
#pragma unroll
    for (int it = 0; it < 8; ++it) {
        float pv = r[it] * inv;
        __nv_bfloat16 h, l;
        split_bf16(pv, h, l);
        ph[ro + tid + it * 256] = h;
        pl[ro + tid + it * 256] = l;
    }
}

// ---------------- kernel_launch --------------------------------------------
extern "C" void kernel_launch(void* const* d_in, const int* in_sizes, int n_in,
                              void* d_out, int out_size)
{
    (void)in_sizes; (void)n_in; (void)out_size;
    const float* x    = (const float*)d_in[0];
    const void*  mask = d_in[1];
    const float* qw   = (const float*)d_in[2];
    const float* kw   = (const float*)d_in[3];
    const float* vw   = (const float*)d_in[4];
    float* out = (float*)d_out;

    __nv_bfloat16 *xh, *xl, *wqh, *wql, *wkh, *wkl, *wvh, *wvl;
    __nv_bfloat16 *qh, *ql, *kh, *kl, *vth, *vtl, *ph, *pl;
    float* sc;
    cudaGetSymbolAddress((void**)&xh,  g_xh);  cudaGetSymbolAddress((void**)&xl,  g_xl);
    cudaGetSymbolAddress((void**)&wqh, g_wqh); cudaGetSymbolAddress((void**)&wql, g_wql);
    cudaGetSymbolAddress((void**)&wkh, g_wkh); cudaGetSymbolAddress((void**)&wkl, g_wkl);
    cudaGetSymbolAddress((void**)&wvh, g_wvh); cudaGetSymbolAddress((void**)&wvl, g_wvl);
    cudaGetSymbolAddress((void**)&qh,  g_qh);  cudaGetSymbolAddress((void**)&ql,  g_ql);
    cudaGetSymbolAddress((void**)&kh,  g_kh);  cudaGetSymbolAddress((void**)&kl,  g_kl);
    cudaGetSymbolAddress((void**)&vth, g_vth); cudaGetSymbolAddress((void**)&vtl, g_vtl);
    cudaGetSymbolAddress((void**)&ph,  g_ph);  cudaGetSymbolAddress((void**)&pl,  g_pl);
    cudaGetSymbolAddress((void**)&sc,  g_sc);

    cudaFuncSetAttribute(gemm3_kernel<0>, cudaFuncAttributeMaxDynamicSharedMemorySize, GEMM_SMEM);
    cudaFuncSetAttribute(gemm3_kernel<1>, cudaFuncAttributeMaxDynamicSharedMemorySize, GEMM_SMEM);
    cudaFuncSetAttribute(gemm3_kernel<2>, cudaFuncAttributeMaxDynamicSharedMemorySize, GEMM_SMEM);

    detect_mask_kernel<<<1, 256>>>((const unsigned char*)mask);

    const size_t nx = (size_t)BB * SS * DD;
    convert_split_kernel<<<(unsigned)(nx / 1024), 256>>>(x, xh, xl, nx);
    wtrans_split_kernel<<<dim3(32, 32), dim3(32, 8)>>>(qw, wqh, wql);
    wtrans_split_kernel<<<dim3(32, 32), dim3(32, 8)>>>(kw, wkh, wkl);
    wtrans_split_kernel<<<dim3(32, 32), dim3(32, 8)>>>(vw, wvh, wvl);

    // Projections: M=8192, N=1024, K=1024
    gemm3_kernel<1><<<dim3(8, 64, 1), 256, GEMM_SMEM>>>(
        xh, xl, wqh, wql, nullptr, qh, ql, DD, DD, 0, 0, 0, 1.0f);
    gemm3_kernel<1><<<dim3(8, 64, 1), 256, GEMM_SMEM>>>(
        xh, xl, wkh, wkl, nullptr, kh, kl, DD, DD, 0, 0, 0, 1.0f);
    gemm3_kernel<2><<<dim3(8, 64, 1), 256, GEMM_SMEM>>>(
        xh, xl, wvh, wvl, nullptr, vth, vtl, DD, DD, 0, 0, 0, 1.0f);

    // Scores: per batch Q[2048,1024] x K^T -> sc f32, scaled
    gemm3_kernel<0><<<dim3(16, 16, BB), 256, GEMM_SMEM>>>(
        qh, ql, kh, kl, sc, nullptr, nullptr, SS, DD,
        (long)SS * DD, (long)SS * DD, (long)SS * SS, 0.03125f);

    // Softmax -> P hi/lo bf16
    softmax_kernel<<<dim3(SS, BB), 256>>>(sc, mask, ph, pl);

    // Out: per batch P[2048,2048] x V^T[1024,2048] -> out f32
    gemm3_kernel<0><<<dim3(8, 16, BB), 256, GEMM_SMEM>>>(
        ph, pl, vth, vtl, out, nullptr, nullptr, DD, SS,
        (long)SS * SS, (long)DD * SS, (long)SS * DD, 1.0f);
}

// round 11
// speedup vs baseline: 2.7328x; 1.1366x over previous
#include <cuda_runtime.h>
#include <cuda_bf16.h>
#include <math_constants.h>
#include <cstdint>

static constexpr int BB = 4, SS = 2048, DD = 1024;

// ---------------- scratch (__device__ globals; no allocs allowed) ----------
__device__ __nv_bfloat16 g_xh[(size_t)BB*SS*DD], g_xl[(size_t)BB*SS*DD];
__device__ __nv_bfloat16 g_wqh[DD*DD], g_wql[DD*DD];
__device__ __nv_bfloat16 g_wkh[DD*DD], g_wkl[DD*DD];
__device__ __nv_bfloat16 g_wvh[DD*DD], g_wvl[DD*DD];
__device__ __nv_bfloat16 g_qh[(size_t)BB*SS*DD], g_ql[(size_t)BB*SS*DD];
__device__ __nv_bfloat16 g_kh[(size_t)BB*SS*DD], g_kl[(size_t)BB*SS*DD];
__device__ __nv_bfloat16 g_vth[(size_t)BB*DD*SS], g_vtl[(size_t)BB*DD*SS];   // V^T per batch
__device__ float         g_sc[(size_t)BB*SS*SS];
__device__ __nv_bfloat16 g_ph[(size_t)BB*SS*SS], g_pl[(size_t)BB*SS*SS];
__device__ int           g_mask_mode;

// ---------------- helpers ---------------------------------------------------
__device__ __forceinline__ uint32_t smem_u32(const void* p) {
    uint32_t a;
    asm("{ .reg .u64 t; cvta.to.shared.u64 t, %1; cvt.u32.u64 %0, t; }" : "=r"(a) : "l"(p));
    return a;
}
__device__ __forceinline__ void ldsm_x4(uint32_t* r, uint32_t addr) {
    asm volatile("ldmatrix.sync.aligned.m8n8.x4.shared.b16 {%0,%1,%2,%3}, [%4];"
                 : "=r"(r[0]), "=r"(r[1]), "=r"(r[2]), "=r"(r[3]) : "r"(addr));
}
__device__ __forceinline__ void mma16816(float* d, const uint32_t* a, const uint32_t* b) {
    asm volatile(
        "mma.sync.aligned.m16n8k16.row.col.f32.bf16.bf16.f32 "
        "{%0,%1,%2,%3}, {%4,%5,%6,%7}, {%8,%9}, {%0,%1,%2,%3};\n"
        : "+f"(d[0]), "+f"(d[1]), "+f"(d[2]), "+f"(d[3])
        : "r"(a[0]), "r"(a[1]), "r"(a[2]), "r"(a[3]), "r"(b[0]), "r"(b[1]));
}
__device__ __forceinline__ void split_bf16(float v, __nv_bfloat16& h, __nv_bfloat16& l) {
    h = __float2bfloat16(v);
    l = __float2bfloat16(v - __bfloat162float(h));
}

// ---------------- GEMM: C = alpha * (Ah+Al)[m,k] x (Bh+Bl)[n,k]^T ----------
// CTA 128x128, KC=64, 8 warps (warp tile 64x32), 3-stage cp.async pipeline.
// Smem rows stride 144B (conflict-free ldmatrix: 4r mod 32 distinct).
// OUT: 0=f32*alpha, 1=bf16 hi/lo, 2=bf16 hi/lo V^T via smem-staged transpose.
static constexpr int KC = 64;
static constexpr int ROWB        = 144;               // 128B data + 16B pad
static constexpr int MAT_BYTES   = 128 * ROWB;        // 18432
static constexpr int STAGE_BYTES = 4 * MAT_BYTES;     // 73728
static constexpr int NSTAGE      = 3;
static constexpr int GEMM_SMEM   = NSTAGE * STAGE_BYTES;   // 221184 (216 KB)

template <int OUT>
__global__ __launch_bounds__(256, 1)
void gemm3_kernel(const __nv_bfloat16* __restrict__ Ah, const __nv_bfloat16* __restrict__ Al,
                  const __nv_bfloat16* __restrict__ Bh, const __nv_bfloat16* __restrict__ Bl,
                  float* __restrict__ Cf, __nv_bfloat16* __restrict__ Ch,
                  __nv_bfloat16* __restrict__ Cl,
                  int N, int K, long sA, long sB, long sC, float alpha)
{
    extern __shared__ char smem[];
    const uint32_t sb = smem_u32(smem);
    const int tid = threadIdx.x, lane = tid & 31, wid = tid >> 5;
    const int wm = wid & 1, wn = wid >> 1;             // warp tile: rows wm*64, cols wn*32
    const int z = blockIdx.z;
    const int tileM = blockIdx.y * 128, tileN = blockIdx.x * 128;

    const char* gA[2] = { (const char*)(Ah + (size_t)z*sA + (size_t)tileM*K),
                          (const char*)(Al + (size_t)z*sA + (size_t)tileM*K) };
    const char* gB[2] = { (const char*)(Bh + (size_t)z*sB + (size_t)tileN*K),
                          (const char*)(Bl + (size_t)z*sB + (size_t)tileN*K) };

    const int nch = K / KC;

#define CP16(dst, src) \
    asm volatile("cp.async.cg.shared.global [%0], [%1], 16;" :: "r"(dst), "l"(src) : "memory")

    // 128 rows x 8 segs(16B) per matrix = 1024 units; 256 threads x 4 iters
#define LOAD_CHUNK(c, stage) do {                                             \
    const uint32_t st_ = sb + (uint32_t)(stage) * STAGE_BYTES;                \
    const size_t ko_ = (size_t)(c) * KC * 2;                                  \
    _Pragma("unroll")                                                         \
    for (int it_ = 0; it_ < 4; ++it_) {                                       \
        const int u_ = tid + it_ * 256;                                       \
        const int r_ = u_ >> 3, sg_ = u_ & 7;                                 \
        const uint32_t doff_ = (uint32_t)(r_ * ROWB + sg_ * 16);              \
        const size_t soff_ = ((size_t)r_ * K + sg_ * 8) * 2 + ko_;            \
        CP16(st_ + 0*MAT_BYTES + doff_, gA[0] + soff_);                       \
        CP16(st_ + 1*MAT_BYTES + doff_, gA[1] + soff_);                       \
        CP16(st_ + 2*MAT_BYTES + doff_, gB[0] + soff_);                       \
        CP16(st_ + 3*MAT_BYTES + doff_, gB[1] + soff_);                       \
    }                                                                         \
    asm volatile("cp.async.commit_group;" ::: "memory");                      \
} while (0)

    LOAD_CHUNK(0, 0);
    LOAD_CHUNK(1, 1);

    float acc[16][4];
#pragma unroll
    for (int i = 0; i < 16; ++i)
#pragma unroll
        for (int j = 0; j < 4; ++j) acc[i][j] = 0.0f;

    // ldmatrix per-lane address components (PTX fragment tables)
    const int arow = wm * 64 + (lane & 7) + ((lane >> 3) & 1) * 8;
    const int acol = ((lane >> 4) & 1) * 16;           // bytes (k+8 -> +16B)
    const int brow = wn * 32 + (lane & 7) + ((lane >> 4) & 1) * 8;
    const int bcol = ((lane >> 3) & 1) * 16;

#pragma unroll 1
    for (int c = 0; c < nch; ++c) {
        // prefetch chunk c+2 into stage (c+2)%3 (last used by chunk c-1, synced)
        if (c + 2 < nch) {
            LOAD_CHUNK(c + 2, (c + 2) % 3);
            asm volatile("cp.async.wait_group 2;" ::: "memory");   // chunk c done
        } else if (c + 1 < nch) {
            asm volatile("cp.async.wait_group 1;" ::: "memory");
        } else {
            asm volatile("cp.async.wait_group 0;" ::: "memory");
        }
        __syncthreads();

        const uint32_t st = sb + (uint32_t)(c % 3) * STAGE_BYTES;
#pragma unroll
        for (int ks = 0; ks < 4; ++ks) {
            const int kb = ks * 32;                    // 16 bf16 = 32 B
            uint32_t ah[4][4], al[4][4], bh[2][4], bl[2][4];
#pragma unroll
            for (int mt = 0; mt < 4; ++mt) {
                const uint32_t ad = st + (uint32_t)((arow + mt * 16) * ROWB + kb + acol);
                ldsm_x4(ah[mt], ad);
                ldsm_x4(al[mt], ad + MAT_BYTES);
            }
#pragma unroll
            for (int bt = 0; bt < 2; ++bt) {
                const uint32_t bd = st + 2 * MAT_BYTES +
                                    (uint32_t)((brow + bt * 16) * ROWB + kb + bcol);
                ldsm_x4(bh[bt], bd);
                ldsm_x4(bl[bt], bd + MAT_BYTES);
            }
#pragma unroll
            for (int mt = 0; mt < 4; ++mt)
#pragma unroll
                for (int nt = 0; nt < 4; ++nt) {
                    float* d = acc[mt * 4 + nt];
                    const uint32_t* bhp = &bh[nt >> 1][(nt & 1) * 2];
                    const uint32_t* blp = &bl[nt >> 1][(nt & 1) * 2];
                    mma16816(d, ah[mt], bhp);
                    mma16816(d, ah[mt], blp);
                    mma16816(d, al[mt], bhp);
                }
        }
        __syncthreads();   // stage c%3 reusable for chunk c+3's load next iter
    }
#undef LOAD_CHUNK
#undef CP16

    // ---------------- epilogue ----------------
    if (OUT == 2) {
        // Stage tile transposed in smem ([n][m], pitch 132 f32), then write
        // V^T coalesced: 64 contiguous bf16 (128B) per thread per array.
        float* smT = reinterpret_cast<float*>(smem);
        const int r0l = wm * 64 + (lane >> 2);
#pragma unroll
        for (int mt = 0; mt < 4; ++mt)
#pragma unroll
            for (int nt = 0; nt < 4; ++nt) {
                const float* d = acc[mt * 4 + nt];
                const int rl = r0l + mt * 16;
                const int cl = wn * 32 + nt * 8 + (lane & 3) * 2;
                smT[cl * 132 + rl]           = d[0];
                smT[(cl + 1) * 132 + rl]     = d[1];
                smT[cl * 132 + rl + 8]       = d[2];
                smT[(cl + 1) * 132 + rl + 8] = d[3];
            }
        __syncthreads();

        const int col = tid >> 1, half = tid & 1;      // 128 cols x 2 halves
        const int mb = tileM >> 11;
        const int s0 = (tileM & (SS - 1)) + half * 64;
        const float* src = smT + col * 132 + half * 64;
        __align__(16) __nv_bfloat162 bufH[32], bufL[32];
#pragma unroll
        for (int j = 0; j < 32; ++j) {
            __nv_bfloat16 h0, l0, h1, l1;
            split_bf16(src[2 * j], h0, l0);
            split_bf16(src[2 * j + 1], h1, l1);
            bufH[j] = __halves2bfloat162(h0, h1);
            bufL[j] = __halves2bfloat162(l0, l1);
        }
        const size_t o = ((size_t)mb * DD + (tileN + col)) * SS + s0;
        uint4* dh = reinterpret_cast<uint4*>(Ch + o);
        uint4* dl = reinterpret_cast<uint4*>(Cl + o);
        const uint4* sh = reinterpret_cast<const uint4*>(bufH);
        const uint4* sl = reinterpret_cast<const uint4*>(bufL);
#pragma unroll
        for (int j = 0; j < 8; ++j) { dh[j] = sh[j]; dl[j] = sl[j]; }
        return;
    }

    const int r0base = tileM + wm * 64, cbase = tileN + wn * 32;
#pragma unroll
    for (int mt = 0; mt < 4; ++mt)
#pragma unroll
        for (int nt = 0; nt < 4; ++nt) {
            const float* d = acc[mt * 4 + nt];
            const int row0 = r0base + mt * 16 + (lane >> 2);
            const int row1 = row0 + 8;
            const int col  = cbase + nt * 8 + (lane & 3) * 2;
            if (OUT == 0) {
                float* base = Cf + (size_t)z * sC;
                float2 v0 = make_float2(alpha * d[0], alpha * d[1]);
                float2 v1 = make_float2(alpha * d[2], alpha * d[3]);
                *reinterpret_cast<float2*>(base + (size_t)row0 * N + col) = v0;
                *reinterpret_cast<float2*>(base + (size_t)row1 * N + col) = v1;
            } else {   // OUT == 1
                __nv_bfloat16 h0, l0, h1, l1, h2, l2, h3, l3;
                split_bf16(d[0], h0, l0); split_bf16(d[1], h1, l1);
                split_bf16(d[2], h2, l2); split_bf16(d[3], h3, l3);
                *reinterpret_cast<__nv_bfloat162*>(Ch + (size_t)row0 * N + col) =
                    __halves2bfloat162(h0, h1);
                *reinterpret_cast<__nv_bfloat162*>(Cl + (size_t)row0 * N + col) =
                    __halves2bfloat162(l0, l1);
                *reinterpret_cast<__nv_bfloat162*>(Ch + (size_t)row1 * N + col) =
                    __halves2bfloat162(h2, h3);
                *reinterpret_cast<__nv_bfloat162*>(Cl + (size_t)row1 * N + col) =
                    __halves2bfloat162(l2, l3);
            }
        }
}

// ---------------- conversions ----------------------------------------------
__global__ void convert_split_kernel(const float* __restrict__ x,
                                     __nv_bfloat16* __restrict__ h,
                                     __nv_bfloat16* __restrict__ l, size_t n)
{
    size_t i = ((size_t)blockIdx.x * 256 + threadIdx.x) * 4;
    if (i >= n) return;
    float4 v = *reinterpret_cast<const float4*>(x + i);
    __nv_bfloat16 h0, l0, h1, l1, h2, l2, h3, l3;
    split_bf16(v.x, h0, l0); split_bf16(v.y, h1, l1);
    split_bf16(v.z, h2, l2); split_bf16(v.w, h3, l3);
    *reinterpret_cast<__nv_bfloat162*>(h + i)     = __halves2bfloat162(h0, h1);
    *reinterpret_cast<__nv_bfloat162*>(h + i + 2) = __halves2bfloat162(h2, h3);
    *reinterpret_cast<__nv_bfloat162*>(l + i)     = __halves2bfloat162(l0, l1);
    *reinterpret_cast<__nv_bfloat162*>(l + i + 2) = __halves2bfloat162(l2, l3);
}

// W [D,D] row-major -> W^T hi/lo bf16 (Th[n*D+k] = W[k][n])
__global__ void wtrans_split_kernel(const float* __restrict__ W,
                                    __nv_bfloat16* __restrict__ Th,
                                    __nv_bfloat16* __restrict__ Tl)
{
    __shared__ float t[32][33];
    const int bx = blockIdx.x * 32, by = blockIdx.y * 32;
    const int tx = threadIdx.x, ty = threadIdx.y;   // 32 x 8
#pragma unroll
    for (int i = 0; i < 32; i += 8)
        t[ty + i][tx] = W[(size_t)(by + ty + i) * DD + bx + tx];
    __syncthreads();
#pragma unroll
    for (int i = 0; i < 32; i += 8) {
        float v = t[tx][ty + i];
        __nv_bfloat16 h, l;
        split_bf16(v, h, l);
        Th[(size_t)(bx + ty + i) * DD + by + tx] = h;
        Tl[(size_t)(bx + ty + i) * DD + by + tx] = l;
    }
}

// ---------------- mask dtype detection (validated in R5) -------------------
__global__ void detect_mask_kernel(const unsigned char* __restrict__ m)
{
    __shared__ int fA, f3, f1;
    if (threadIdx.x == 0) { fA = 0; f3 = 0; f1 = 0; }
    __syncthreads();
    for (int i = threadIdx.x; i < BB * SS; i += 256) {
        unsigned char b = m[i];
        int r = i & 3;
        if (r != 0 && b != 0) fA = 1;
        if (r == 3 && b == 0x3F) f3 = 1;
        if (r == 1 && b == 0x3F) f1 = 1;
    }
    __syncthreads();
    if (threadIdx.x == 0) {
        int mode;
        if (f1)      mode = 3;
        else if (f3) mode = 2;
        else if (fA) mode = 0;
        else         mode = 1;
        g_mask_mode = mode;
    }
}
__device__ __forceinline__ int mask_value(const void* m, long row)
{
    switch (g_mask_mode) {
        case 1:  return ((const int*)m)[row] != 0;
        case 2:  return ((const float*)m)[row] != 0.0f;
        case 3:  return ((const unsigned short*)m)[row] != 0;
        default: return ((const unsigned char*)m)[row] != 0;
    }
}

// ---------------- softmax (fp32 in, bf16 hi/lo out) -------------------------
// Masked rows: fp32 +(-1e9) collapses the row to exactly -1e9 (ulp=64) ->
// exactly uniform softmax, matching the reference bit-behavior.
__global__ __launch_bounds__(256)
void softmax_kernel(const float* __restrict__ sc, const void* __restrict__ mask,
                    __nv_bfloat16* __restrict__ ph, __nv_bfloat16* __restrict__ pl)
{
    const long row = (long)blockIdx.y * SS + blockIdx.x;
    const float* p = sc + (size_t)row * SS;
    const int tid = threadIdx.x, lane = tid & 31, warp = tid >> 5;
    __shared__ float red[8];

    const float madd = mask_value(mask, row) ? 0.0f : -1e9f;

    float r[8];
    float m = -CUDART_INF_F;
#pragma unroll
    for (int it = 0; it < 8; ++it) {
        float s = p[tid + it * 256] + madd;   // fp32 rounding intentional
        r[it] = s;
        m = fmaxf(m, s);
    }
#pragma unroll
    for (int o = 16; o > 0; o >>= 1) m = fmaxf(m, __shfl_xor_sync(0xffffffffu, m, o));
    if (lane == 0) red[warp] = m;
    __syncthreads();
    m = red[lane & 7];
#pragma unroll
    for (int o = 4; o > 0; o >>= 1) m = fmaxf(m, __shfl_xor_sync(0xffffffffu, m, o));
    m = __shfl_sync(0xffffffffu, m, 0);

    float sum = 0.0f;
#pragma unroll
    for (int it = 0; it < 8; ++it) {
        float e = __expf(r[it] - m);
        r[it] = e;
        sum += e;
    }
#pragma unroll
    for (int o = 16; o > 0; o >>= 1) sum += __shfl_xor_sync(0xffffffffu, sum, o);
    __syncthreads();
    if (lane == 0) red[warp] = sum;
    __syncthreads();
    sum = red[lane & 7];
#pragma unroll
    for (int o = 4; o > 0; o >>= 1) sum += __shfl_xor_sync(0xffffffffu, sum, o);
    const float inv = 1.0f / __shfl_sync(0xffffffffu, sum, 0);

    const size_t ro = (size_t)row * SS;
#pragma unroll
    for (int it = 0; it < 8; ++it) {
        float pv = r[it] * inv;
        __nv_bfloat16 h, l;
        split_bf16(pv, h, l);
        ph[ro + tid + it * 256] = h;
        pl[ro + tid + it * 256] = l;
    }
}

// ---------------- kernel_launch --------------------------------------------
extern "C" void kernel_launch(void* const* d_in, const int* in_sizes, int n_in,
                              void* d_out, int out_size)
{
    (void)in_sizes; (void)n_in; (void)out_size;
    const float* x    = (const float*)d_in[0];
    const void*  mask = d_in[1];
    const float* qw   = (const float*)d_in[2];
    const float* kw   = (const float*)d_in[3];
    const float* vw   = (const float*)d_in[4];
    float* out = (float*)d_out;

    __nv_bfloat16 *xh, *xl, *wqh, *wql, *wkh, *wkl, *wvh, *wvl;
    __nv_bfloat16 *qh, *ql, *kh, *kl, *vth, *vtl, *ph, *pl;
    float* sc;
    cudaGetSymbolAddress((void**)&xh,  g_xh);  cudaGetSymbolAddress((void**)&xl,  g_xl);
    cudaGetSymbolAddress((void**)&wqh, g_wqh); cudaGetSymbolAddress((void**)&wql, g_wql);
    cudaGetSymbolAddress((void**)&wkh, g_wkh); cudaGetSymbolAddress((void**)&wkl, g_wkl);
    cudaGetSymbolAddress((void**)&wvh, g_wvh); cudaGetSymbolAddress((void**)&wvl, g_wvl);
    cudaGetSymbolAddress((void**)&qh,  g_qh);  cudaGetSymbolAddress((void**)&ql,  g_ql);
    cudaGetSymbolAddress((void**)&kh,  g_kh);  cudaGetSymbolAddress((void**)&kl,  g_kl);
    cudaGetSymbolAddress((void**)&vth, g_vth); cudaGetSymbolAddress((void**)&vtl, g_vtl);
    cudaGetSymbolAddress((void**)&ph,  g_ph);  cudaGetSymbolAddress((void**)&pl,  g_pl);
    cudaGetSymbolAddress((void**)&sc,  g_sc);

    cudaFuncSetAttribute(gemm3_kernel<0>, cudaFuncAttributeMaxDynamicSharedMemorySize, GEMM_SMEM);
    cudaFuncSetAttribute(gemm3_kernel<1>, cudaFuncAttributeMaxDynamicSharedMemorySize, GEMM_SMEM);
    cudaFuncSetAttribute(gemm3_kernel<2>, cudaFuncAttributeMaxDynamicSharedMemorySize, GEMM_SMEM);

    detect_mask_kernel<<<1, 256>>>((const unsigned char*)mask);

    const size_t nx = (size_t)BB * SS * DD;
    convert_split_kernel<<<(unsigned)(nx / 1024), 256>>>(x, xh, xl, nx);
    wtrans_split_kernel<<<dim3(32, 32), dim3(32, 8)>>>(qw, wqh, wql);
    wtrans_split_kernel<<<dim3(32, 32), dim3(32, 8)>>>(kw, wkh, wkl);
    wtrans_split_kernel<<<dim3(32, 32), dim3(32, 8)>>>(vw, wvh, wvl);

    // Projections: M=8192, N=1024, K=1024
    gemm3_kernel<1><<<dim3(8, 64, 1), 256, GEMM_SMEM>>>(
        xh, xl, wqh, wql, nullptr, qh, ql, DD, DD, 0, 0, 0, 1.0f);
    gemm3_kernel<1><<<dim3(8, 64, 1), 256, GEMM_SMEM>>>(
        xh, xl, wkh, wkl, nullptr, kh, kl, DD, DD, 0, 0, 0, 1.0f);
    gemm3_kernel<2><<<dim3(8, 64, 1), 256, GEMM_SMEM>>>(
        xh, xl, wvh, wvl, nullptr, vth, vtl, DD, DD, 0, 0, 0, 1.0f);

    // Scores: per batch Q[2048,1024] x K^T -> sc f32, scaled
    gemm3_kernel<0><<<dim3(16, 16, BB), 256, GEMM_SMEM>>>(
        qh, ql, kh, kl, sc, nullptr, nullptr, SS, DD,
        (long)SS * DD, (long)SS * DD, (long)SS * SS, 0.03125f);

    // Softmax -> P hi/lo bf16
    softmax_kernel<<<dim3(SS, BB), 256>>>(sc, mask, ph, pl);

    // Out: per batch P[2048,2048] x V^T[1024,2048] -> out f32
    gemm3_kernel<0><<<dim3(8, 16, BB), 256, GEMM_SMEM>>>(
        ph, pl, vth, vtl, out, nullptr, nullptr, DD, SS,
        (long)SS * SS, (long)DD * SS, (long)SS * DD, 1.0f);
}

// round 13
// speedup vs baseline: 2.7456x; 1.0047x over previous
#include <cuda_runtime.h>
#include <cuda_bf16.h>
#include <math_constants.h>
#include <cstdint>

static constexpr int BB = 4, SS = 2048, DD = 1024;

// ---------------- scratch (__device__ globals; no allocs allowed) ----------
__device__ __nv_bfloat16 g_xh[(size_t)BB*SS*DD], g_xl[(size_t)BB*SS*DD];
__device__ __nv_bfloat16 g_wqh[DD*DD], g_wql[DD*DD];
__device__ __nv_bfloat16 g_wkh[DD*DD], g_wkl[DD*DD];
__device__ __nv_bfloat16 g_wvh[DD*DD], g_wvl[DD*DD];
__device__ __nv_bfloat16 g_qh[(size_t)BB*SS*DD], g_ql[(size_t)BB*SS*DD];
__device__ __nv_bfloat16 g_kh[(size_t)BB*SS*DD], g_kl[(size_t)BB*SS*DD];
__device__ __nv_bfloat16 g_vth[(size_t)BB*DD*SS], g_vtl[(size_t)BB*DD*SS];   // V^T per batch
__device__ float         g_sc[(size_t)BB*SS*SS];
__device__ __nv_bfloat16 g_ph[(size_t)BB*SS*SS], g_pl[(size_t)BB*SS*SS];
__device__ int           g_mask_mode;

// ---------------- helpers ---------------------------------------------------
__device__ __forceinline__ uint32_t smem_u32(const void* p) {
    uint32_t a;
    asm("{ .reg .u64 t; cvta.to.shared.u64 t, %1; cvt.u32.u64 %0, t; }" : "=r"(a) : "l"(p));
    return a;
}
__device__ __forceinline__ void ldsm_x4(uint32_t* r, uint32_t addr) {
    asm volatile("ldmatrix.sync.aligned.m8n8.x4.shared.b16 {%0,%1,%2,%3}, [%4];"
                 : "=r"(r[0]), "=r"(r[1]), "=r"(r[2]), "=r"(r[3]) : "r"(addr));
}
__device__ __forceinline__ void mma16816(float* d, const uint32_t* a, const uint32_t* b) {
    asm volatile(
        "mma.sync.aligned.m16n8k16.row.col.f32.bf16.bf16.f32 "
        "{%0,%1,%2,%3}, {%4,%5,%6,%7}, {%8,%9}, {%0,%1,%2,%3};\n"
        : "+f"(d[0]), "+f"(d[1]), "+f"(d[2]), "+f"(d[3])
        : "r"(a[0]), "r"(a[1]), "r"(a[2]), "r"(a[3]), "r"(b[0]), "r"(b[1]));
}
__device__ __forceinline__ void split_bf16(float v, __nv_bfloat16& h, __nv_bfloat16& l) {
    h = __float2bfloat16(v);
    l = __float2bfloat16(v - __bfloat162float(h));
}

// ---------------- GEMM: C = alpha * (Ah+Al)[m,k] x (Bh+Bl)[n,k]^T ----------
// CTA 128x128, KC=64, 8 warps (warp tile 64x32), 3-stage cp.async pipeline.
// Smem rows stride 144B (conflict-free ldmatrix: 4r mod 32 distinct).
// OUT: 0=f32*alpha, 1=bf16 hi/lo, 2=bf16 hi/lo V^T via smem-staged transpose.
static constexpr int KC = 64;
static constexpr int ROWB        = 144;               // 128B data + 16B pad
static constexpr int MAT_BYTES   = 128 * ROWB;        // 18432
static constexpr int STAGE_BYTES = 4 * MAT_BYTES;     // 73728
static constexpr int NSTAGE      = 3;
static constexpr int GEMM_SMEM   = NSTAGE * STAGE_BYTES;   // 221184 (216 KB)

template <int OUT>
__global__ __launch_bounds__(256, 1)
void gemm3_kernel(const __nv_bfloat16* __restrict__ Ah, const __nv_bfloat16* __restrict__ Al,
                  const __nv_bfloat16* __restrict__ Bh, const __nv_bfloat16* __restrict__ Bl,
                  float* __restrict__ Cf, __nv_bfloat16* __restrict__ Ch,
                  __nv_bfloat16* __restrict__ Cl,
                  int N, int K, long sA, long sB, long sC, float alpha)
{
    extern __shared__ char smem[];
    const uint32_t sb = smem_u32(smem);
    const int tid = threadIdx.x, lane = tid & 31, wid = tid >> 5;
    const int wm = wid & 1, wn = wid >> 1;             // warp tile: rows wm*64, cols wn*32
    const int z = blockIdx.z;
    const int tileM = blockIdx.y * 128, tileN = blockIdx.x * 128;

    const char* gA[2] = { (const char*)(Ah + (size_t)z*sA + (size_t)tileM*K),
                          (const char*)(Al + (size_t)z*sA + (size_t)tileM*K) };
    const char* gB[2] = { (const char*)(Bh + (size_t)z*sB + (size_t)tileN*K),
                          (const char*)(Bl + (size_t)z*sB + (size_t)tileN*K) };

    const int nch = K / KC;

#define CP16(dst, src) \
    asm volatile("cp.async.cg.shared.global [%0], [%1], 16;" :: "r"(dst), "l"(src) : "memory")

    // 128 rows x 8 segs(16B) per matrix = 1024 units; 256 threads x 4 iters
#define LOAD_CHUNK(c, stage) do {                                             \
    const uint32_t st_ = sb + (uint32_t)(stage) * STAGE_BYTES;                \
    const size_t ko_ = (size_t)(c) * KC * 2;                                  \
    _Pragma("unroll")                                                         \
    for (int it_ = 0; it_ < 4; ++it_) {                                       \
        const int u_ = tid + it_ * 256;                                       \
        const int r_ = u_ >> 3, sg_ = u_ & 7;                                 \
        const uint32_t doff_ = (uint32_t)(r_ * ROWB + sg_ * 16);              \
        const size_t soff_ = ((size_t)r_ * K + sg_ * 8) * 2 + ko_;            \
        CP16(st_ + 0*MAT_BYTES + doff_, gA[0] + soff_);                       \
        CP16(st_ + 1*MAT_BYTES + doff_, gA[1] + soff_);                       \
        CP16(st_ + 2*MAT_BYTES + doff_, gB[0] + soff_);                       \
        CP16(st_ + 3*MAT_BYTES + doff_, gB[1] + soff_);                       \
    }                                                                         \
    asm volatile("cp.async.commit_group;" ::: "memory");                      \
} while (0)

    LOAD_CHUNK(0, 0);
    LOAD_CHUNK(1, 1);

    float acc[16][4];
#pragma unroll
    for (int i = 0; i < 16; ++i)
#pragma unroll
        for (int j = 0; j < 4; ++j) acc[i][j] = 0.0f;

    // ldmatrix per-lane address components (PTX fragment tables)
    const int arow = wm * 64 + (lane & 7) + ((lane >> 3) & 1) * 8;
    const int acol = ((lane >> 4) & 1) * 16;           // bytes (k+8 -> +16B)
    const int brow = wn * 32 + (lane & 7) + ((lane >> 4) & 1) * 8;
    const int bcol = ((lane >> 3) & 1) * 16;

#pragma unroll 1
    for (int c = 0; c < nch; ++c) {
        // prefetch chunk c+2 into stage (c+2)%3 (last used by chunk c-1, synced)
        if (c + 2 < nch) {
            LOAD_CHUNK(c + 2, (c + 2) % 3);
            asm volatile("cp.async.wait_group 2;" ::: "memory");   // chunk c done
        } else if (c + 1 < nch) {
            asm volatile("cp.async.wait_group 1;" ::: "memory");
        } else {
            asm volatile("cp.async.wait_group 0;" ::: "memory");
        }
        __syncthreads();

        const uint32_t st = sb + (uint32_t)(c % 3) * STAGE_BYTES;
#pragma unroll
        for (int ks = 0; ks < 4; ++ks) {
            const int kb = ks * 32;                    // 16 bf16 = 32 B
            uint32_t ah[4][4], al[4][4], bh[2][4], bl[2][4];
#pragma unroll
            for (int bt = 0; bt < 2; ++bt) {
                const uint32_t bd = st + 2 * MAT_BYTES +
                                    (uint32_t)((brow + bt * 16) * ROWB + kb + bcol);
                ldsm_x4(bh[bt], bd);
                ldsm_x4(bl[bt], bd + MAT_BYTES);
            }
#pragma unroll
            for (int mt = 0; mt < 4; ++mt) {
                const uint32_t ad = st + (uint32_t)((arow + mt * 16) * ROWB + kb + acol);
                ldsm_x4(ah[mt], ad);
                ldsm_x4(al[mt], ad + MAT_BYTES);
            }
#pragma unroll
            for (int mt = 0; mt < 4; ++mt)
#pragma unroll
                for (int nt = 0; nt < 4; ++nt) {
                    float* d = acc[mt * 4 + nt];
                    const uint32_t* bhp = &bh[nt >> 1][(nt & 1) * 2];
                    const uint32_t* blp = &bl[nt >> 1][(nt & 1) * 2];
                    mma16816(d, ah[mt], bhp);
                    mma16816(d, ah[mt], blp);
                    mma16816(d, al[mt], bhp);
                }
        }
        __syncthreads();   // stage c%3 reusable for chunk c+3's load next iter
    }
#undef LOAD_CHUNK
#undef CP16

    // ---------------- epilogue ----------------
    if (OUT == 2) {
        // Stage tile transposed in smem ([n][m], pitch 132 f32), then write
        // V^T coalesced: 64 contiguous bf16 (128B) per thread per array.
        float* smT = reinterpret_cast<float*>(smem);
        const int r0l = wm * 64 + (lane >> 2);
#pragma unroll
        for (int mt = 0; mt < 4; ++mt)
#pragma unroll
            for (int nt = 0; nt < 4; ++nt) {
                const float* d = acc[mt * 4 + nt];
                const int rl = r0l + mt * 16;
                const int cl = wn * 32 + nt * 8 + (lane & 3) * 2;
                smT[cl * 132 + rl]           = d[0];
                smT[(cl + 1) * 132 + rl]     = d[1];
                smT[cl * 132 + rl + 8]       = d[2];
                smT[(cl + 1) * 132 + rl + 8] = d[3];
            }
        __syncthreads();

        const int col = tid >> 1, half = tid & 1;      // 128 cols x 2 halves
        const int mb = tileM >> 11;
        const int s0 = (tileM & (SS - 1)) + half * 64;
        const float* src = smT + col * 132 + half * 64;
        __align__(16) __nv_bfloat162 bufH[32], bufL[32];
#pragma unroll
        for (int j = 0; j < 32; ++j) {
            __nv_bfloat16 h0, l0, h1, l1;
            split_bf16(src[2 * j], h0, l0);
            split_bf16(src[2 * j + 1], h1, l1);
            bufH[j] = __halves2bfloat162(h0, h1);
            bufL[j] = __halves2bfloat162(l0, l1);
        }
        const size_t o = ((size_t)mb * DD + (tileN + col)) * SS + s0;
        uint4* dh = reinterpret_cast<uint4*>(Ch + o);
        uint4* dl = reinterpret_cast<uint4*>(Cl + o);
        const uint4* sh = reinterpret_cast<const uint4*>(bufH);
        const uint4* sl = reinterpret_cast<const uint4*>(bufL);
#pragma unroll
        for (int j = 0; j < 8; ++j) { dh[j] = sh[j]; dl[j] = sl[j]; }
        return;
    }

    const int r0base = tileM + wm * 64, cbase = tileN + wn * 32;
#pragma unroll
    for (int mt = 0; mt < 4; ++mt)
#pragma unroll
        for (int nt = 0; nt < 4; ++nt) {
            const float* d = acc[mt * 4 + nt];
            const int row0 = r0base + mt * 16 + (lane >> 2);
            const int row1 = row0 + 8;
            const int col  = cbase + nt * 8 + (lane & 3) * 2;
            if (OUT == 0) {
                float* base = Cf + (size_t)z * sC;
                float2 v0 = make_float2(alpha * d[0], alpha * d[1]);
                float2 v1 = make_float2(alpha * d[2], alpha * d[3]);
                *reinterpret_cast<float2*>(base + (size_t)row0 * N + col) = v0;
                *reinterpret_cast<float2*>(base + (size_t)row1 * N + col) = v1;
            } else {   // OUT == 1
                __nv_bfloat16 h0, l0, h1, l1, h2, l2, h3, l3;
                split_bf16(d[0], h0, l0); split_bf16(d[1], h1, l1);
                split_bf16(d[2], h2, l2); split_bf16(d[3], h3, l3);
                *reinterpret_cast<__nv_bfloat162*>(Ch + (size_t)row0 * N + col) =
                    __halves2bfloat162(h0, h1);
                *reinterpret_cast<__nv_bfloat162*>(Cl + (size_t)row0 * N + col) =
                    __halves2bfloat162(l0, l1);
                *reinterpret_cast<__nv_bfloat162*>(Ch + (size_t)row1 * N + col) =
                    __halves2bfloat162(h2, h3);
                *reinterpret_cast<__nv_bfloat162*>(Cl + (size_t)row1 * N + col) =
                    __halves2bfloat162(l2, l3);
            }
        }
}

// ---------------- conversions ----------------------------------------------
__global__ void convert_split_kernel(const float* __restrict__ x,
                                     __nv_bfloat16* __restrict__ h,
                                     __nv_bfloat16* __restrict__ l, size_t n)
{
    size_t i = ((size_t)blockIdx.x * 256 + threadIdx.x) * 4;
    if (i >= n) return;
    float4 v = *reinterpret_cast<const float4*>(x + i);
    __nv_bfloat16 h0, l0, h1, l1, h2, l2, h3, l3;
    split_bf16(v.x, h0, l0); split_bf16(v.y, h1, l1);
    split_bf16(v.z, h2, l2); split_bf16(v.w, h3, l3);
    *reinterpret_cast<__nv_bfloat162*>(h + i)     = __halves2bfloat162(h0, h1);
    *reinterpret_cast<__nv_bfloat162*>(h + i + 2) = __halves2bfloat162(h2, h3);
    *reinterpret_cast<__nv_bfloat162*>(l + i)     = __halves2bfloat162(l0, l1);
    *reinterpret_cast<__nv_bfloat162*>(l + i + 2) = __halves2bfloat162(l2, l3);
}

// All three weights W [D,D] row-major -> W^T hi/lo bf16, one launch (grid.z=3)
__global__ void wtrans3_split_kernel(const float* __restrict__ W0,
                                     const float* __restrict__ W1,
                                     const float* __restrict__ W2,
                                     __nv_bfloat16* __restrict__ Th0,
                                     __nv_bfloat16* __restrict__ Tl0,
                                     __nv_bfloat16* __restrict__ Th1,
                                     __nv_bfloat16* __restrict__ Tl1,
                                     __nv_bfloat16* __restrict__ Th2,
                                     __nv_bfloat16* __restrict__ Tl2)
{
    const int zz = blockIdx.z;
    const float* W = (zz == 0) ? W0 : (zz == 1) ? W1 : W2;
    __nv_bfloat16* Th = (zz == 0) ? Th0 : (zz == 1) ? Th1 : Th2;
    __nv_bfloat16* Tl = (zz == 0) ? Tl0 : (zz == 1) ? Tl1 : Tl2;

    __shared__ float t[32][33];
    const int bx = blockIdx.x * 32, by = blockIdx.y * 32;
    const int tx = threadIdx.x, ty = threadIdx.y;   // 32 x 8
#pragma unroll
    for (int i = 0; i < 32; i += 8)
        t[ty + i][tx] = W[(size_t)(by + ty + i) * DD + bx + tx];
    __syncthreads();
#pragma unroll
    for (int i = 0; i < 32; i += 8) {
        float v = t[tx][ty + i];
        __nv_bfloat16 h, l;
        split_bf16(v, h, l);
        Th[(size_t)(bx + ty + i) * DD + by + tx] = h;
        Tl[(size_t)(bx + ty + i) * DD + by + tx] = l;
    }
}

// ---------------- mask dtype detection (validated in R5) -------------------
__global__ void detect_mask_kernel(const unsigned char* __restrict__ m)
{
    __shared__ int fA, f3, f1;
    if (threadIdx.x == 0) { fA = 0; f3 = 0; f1 = 0; }
    __syncthreads();
    for (int i = threadIdx.x; i < BB * SS; i += 256) {
        unsigned char b = m[i];
        int r = i & 3;
        if (r != 0 && b != 0) fA = 1;
        if (r == 3 && b == 0x3F) f3 = 1;
        if (r == 1 && b == 0x3F) f1 = 1;
    }
    __syncthreads();
    if (threadIdx.x == 0) {
        int mode;
        if (f1)      mode = 3;
        else if (f3) mode = 2;
        else if (fA) mode = 0;
        else         mode = 1;
        g_mask_mode = mode;
    }
}
__device__ __forceinline__ int mask_value(const void* m, long row)
{
    switch (g_mask_mode) {
        case 1:  return ((const int*)m)[row] != 0;
        case 2:  return ((const float*)m)[row] != 0.0f;
        case 3:  return ((const unsigned short*)m)[row] != 0;
        default: return ((const unsigned char*)m)[row] != 0;
    }
}

// ---------------- softmax (fp32 in, bf16 hi/lo out) -------------------------
// Masked rows: fp32 +(-1e9) collapses the row to exactly -1e9 (ulp=64) ->
// exactly uniform softmax, matching the reference bit-behavior.
// Each thread handles 2 consecutive elems x 4 iters -> vectorized ld/st.
__global__ __launch_bounds__(256)
void softmax_kernel(const float* __restrict__ sc, const void* __restrict__ mask,
                    __nv_bfloat16* __restrict__ ph, __nv_bfloat16* __restrict__ pl)
{
    const long row = (long)blockIdx.y * SS + blockIdx.x;
    const float* p = sc + (size_t)row * SS;
    const int tid = threadIdx.x, lane = tid & 31, warp = tid >> 5;
    __shared__ float red[8];

    const float madd = mask_value(mask, row) ? 0.0f : -1e9f;

    float2 r[4];
    float m = -CUDART_INF_F;
#pragma unroll
    for (int it = 0; it < 4; ++it) {
        float2 v = *reinterpret_cast<const float2*>(p + it * 512 + tid * 2);
        v.x += madd; v.y += madd;      // fp32 rounding intentional
        r[it] = v;
        m = fmaxf(m, fmaxf(v.x, v.y));
    }
#pragma unroll
    for (int o = 16; o > 0; o >>= 1) m = fmaxf(m, __shfl_xor_sync(0xffffffffu, m, o));
    if (lane == 0) red[warp] = m;
    __syncthreads();
    m = red[lane & 7];
#pragma unroll
    for (int o = 4; o > 0; o >>= 1) m = fmaxf(m, __shfl_xor_sync(0xffffffffu, m, o));
    m = __shfl_sync(0xffffffffu, m, 0);

    float sum = 0.0f;
#pragma unroll
    for (int it = 0; it < 4; ++it) {
        r[it].x = __expf(r[it].x - m);
        r[it].y = __expf(r[it].y - m);
        sum += r[it].x + r[it].y;
    }
#pragma unroll
    for (int o = 16; o > 0; o >>= 1) sum += __shfl_xor_sync(0xffffffffu, sum, o);
    __syncthreads();
    if (lane == 0) red[warp] = sum;
    __syncthreads();
    sum = red[lane & 7];
#pragma unroll
    for (int o = 4; o > 0; o >>= 1) sum += __shfl_xor_sync(0xffffffffu, sum, o);
    const float inv = 1.0f / __shfl_sync(0xffffffffu, sum, 0);

    const size_t ro = (size_t)row * SS;
#pragma unroll
    for (int it = 0; it < 4; ++it) {
        float p0 = r[it].x * inv, p1 = r[it].y * inv;
        __nv_bfloat16 h0, l0, h1, l1;
        split_bf16(p0, h0, l0);
        split_bf16(p1, h1, l1);
        const size_t o = ro + it * 512 + tid * 2;
        *reinterpret_cast<__nv_bfloat162*>(ph + o) = __halves2bfloat162(h0, h1);
        *reinterpret_cast<__nv_bfloat162*>(pl + o) = __halves2bfloat162(l0, l1);
    }
}

// ---------------- kernel_launch --------------------------------------------
extern "C" void kernel_launch(void* const* d_in, const int* in_sizes, int n_in,
                              void* d_out, int out_size)
{
    (void)in_sizes; (void)n_in; (void)out_size;
    const float* x    = (const float*)d_in[0];
    const void*  mask = d_in[1];
    const float* qw   = (const float*)d_in[2];
    const float* kw   = (const float*)d_in[3];
    const float* vw   = (const float*)d_in[4];
    float* out = (float*)d_out;

    __nv_bfloat16 *xh, *xl, *wqh, *wql, *wkh, *wkl, *wvh, *wvl;
    __nv_bfloat16 *qh, *ql, *kh, *kl, *vth, *vtl, *ph, *pl;
    float* sc;
    cudaGetSymbolAddress((void**)&xh,  g_xh);  cudaGetSymbolAddress((void**)&xl,  g_xl);
    cudaGetSymbolAddress((void**)&wqh, g_wqh); cudaGetSymbolAddress((void**)&wql, g_wql);
    cudaGetSymbolAddress((void**)&wkh, g_wkh); cudaGetSymbolAddress((void**)&wkl, g_wkl);
    cudaGetSymbolAddress((void**)&wvh, g_wvh); cudaGetSymbolAddress((void**)&wvl, g_wvl);
    cudaGetSymbolAddress((void**)&qh,  g_qh);  cudaGetSymbolAddress((void**)&ql,  g_ql);
    cudaGetSymbolAddress((void**)&kh,  g_kh);  cudaGetSymbolAddress((void**)&kl,  g_kl);
    cudaGetSymbolAddress((void**)&vth, g_vth); cudaGetSymbolAddress((void**)&vtl, g_vtl);
    cudaGetSymbolAddress((void**)&ph,  g_ph);  cudaGetSymbolAddress((void**)&pl,  g_pl);
    cudaGetSymbolAddress((void**)&sc,  g_sc);

    cudaFuncSetAttribute(gemm3_kernel<0>, cudaFuncAttributeMaxDynamicSharedMemorySize, GEMM_SMEM);
    cudaFuncSetAttribute(gemm3_kernel<1>, cudaFuncAttributeMaxDynamicSharedMemorySize, GEMM_SMEM);
    cudaFuncSetAttribute(gemm3_kernel<2>, cudaFuncAttributeMaxDynamicSharedMemorySize, GEMM_SMEM);

    // 1: mask dtype detect
    detect_mask_kernel<<<1, 256>>>((const unsigned char*)mask);
    // 2: x -> hi/lo split
    const size_t nx = (size_t)BB * SS * DD;
    convert_split_kernel<<<(unsigned)(nx / 1024), 256>>>(x, xh, xl, nx);
    // 3: all weight transposes in one launch
    wtrans3_split_kernel<<<dim3(32, 32, 3), dim3(32, 8)>>>(
        qw, kw, vw, wqh, wql, wkh, wkl, wvh, wvl);

    // 4,5,6: projections (M=8192, N=1024, K=1024). Launch #5 = K proj (ncu target).
    gemm3_kernel<1><<<dim3(8, 64, 1), 256, GEMM_SMEM>>>(
        xh, xl, wqh, wql, nullptr, qh, ql, DD, DD, 0, 0, 0, 1.0f);
    gemm3_kernel<1><<<dim3(8, 64, 1), 256, GEMM_SMEM>>>(
        xh, xl, wkh, wkl, nullptr, kh, kl, DD, DD, 0, 0, 0, 1.0f);
    gemm3_kernel<2><<<dim3(8, 64, 1), 256, GEMM_SMEM>>>(
        xh, xl, wvh, wvl, nullptr, vth, vtl, DD, DD, 0, 0, 0, 1.0f);

    // 7: scores per batch Q[2048,1024] x K^T -> sc f32, scaled
    gemm3_kernel<0><<<dim3(16, 16, BB), 256, GEMM_SMEM>>>(
        qh, ql, kh, kl, sc, nullptr, nullptr, SS, DD,
        (long)SS * DD, (long)SS * DD, (long)SS * SS, 0.03125f);

    // 8: softmax -> P hi/lo bf16
    softmax_kernel<<<dim3(SS, BB), 256>>>(sc, mask, ph, pl);

    // 9: out per batch P[2048,2048] x V^T[1024,2048] -> out f32
    gemm3_kernel<0><<<dim3(8, 16, BB), 256, GEMM_SMEM>>>(
        ph, pl, vth, vtl, out, nullptr, nullptr, DD, SS,
        (long)SS * SS, (long)DD * SS, (long)SS * DD, 1.0f);
}